// round 14
// baseline (speedup 1.0000x reference)
#include <cuda_runtime.h>
#include <cuda_bf16.h>
#include <cuda_fp16.h>
#include <cstdint>

#define NTOK 16384
#define HDIM 4096
#define NEXP 64
#define BM   128
#define KC   64
#define SPLITK 2
#define KSPAN (HDIM / SPLITK)        // 2048
#define NCHUNK (KSPAN / KC)          // 32
#define NKS    (HDIM / 16)           // 256 global k-steps
#define XSB 72                        // x smem row stride (fp16 units; 144B)
#define X_SLOT (BM * XSB)             // 9216 halfs = 18432B per slot
#define W_SLOT 1024                   // uint4 per slot: [4 ks][4 tg][64 e]
#define SMEM_BYTES (2 * X_SLOT * 2 + 2 * W_SLOT * 16)   // 36864 + 32768 = 69632

#define FLT_MIN_NORMAL 1.17549435e-38f
#define MARGIN 4e-3f

// W packed fp16 hi/lo in MMA-fragment order: [ksg(256)][e(64)][tg(4)] of
// uint4{h01,h89,l01,l89} (fp16x2 pairs for k=16ks+2tg,+1 and +8,+9). 1MB.
__device__ uint4 g_w_pack[NKS * NEXP * 4];
// Split-K partial logits [SPLITK][NTOK][NEXP] fp32 = 8MB.
__device__ float g_part[SPLITK * NTOK * NEXP];
// Margin-flagged tokens for exact recompute.
__device__ int g_nflag;
__device__ int g_flags[NTOK];

__global__ void prep_w_kernel(const float* __restrict__ w) {
    int i = blockIdx.x * blockDim.x + threadIdx.x;   // 0..65535
    if (i == 0) g_nflag = 0;
    if (i >= NKS * NEXP * 4) return;
    int tg  = i & 3;
    int e   = (i >> 2) & 63;
    int ksg = i >> 8;
    int kb  = ksg * 16 + tg * 2;
    float v[4] = { w[(size_t)e * HDIM + kb],     w[(size_t)e * HDIM + kb + 1],
                   w[(size_t)e * HDIM + kb + 8], w[(size_t)e * HDIM + kb + 9] };
    __half h[4], l[4];
#pragma unroll
    for (int j = 0; j < 4; j++) {
        h[j] = __float2half_rn(v[j]);
        l[j] = __float2half_rn(v[j] - __half2float(h[j]));
    }
    uint4 p;
    p.x = ((uint32_t)__half_as_ushort(h[1]) << 16) | __half_as_ushort(h[0]);
    p.y = ((uint32_t)__half_as_ushort(h[3]) << 16) | __half_as_ushort(h[2]);
    p.z = ((uint32_t)__half_as_ushort(l[1]) << 16) | __half_as_ushort(l[0]);
    p.w = ((uint32_t)__half_as_ushort(l[3]) << 16) | __half_as_ushort(l[2]);
    g_w_pack[i] = p;
}

__device__ __forceinline__ void mma_fp16(float* c, const uint32_t* a,
                                         uint32_t b0, uint32_t b1) {
    asm volatile(
        "mma.sync.aligned.m16n8k16.row.col.f32.f16.f16.f32 "
        "{%0,%1,%2,%3}, {%4,%5,%6,%7}, {%8,%9}, {%0,%1,%2,%3};\n"
        : "+f"(c[0]), "+f"(c[1]), "+f"(c[2]), "+f"(c[3])
        : "r"(a[0]), "r"(a[1]), "r"(a[2]), "r"(a[3]), "r"(b0), "r"(b1));
}

__device__ __forceinline__ uint32_t f2sortable(float f) {
    uint32_t b = __float_as_uint(f);
    return b ^ (((int32_t)b >> 31) | 0x80000000u);
}
__device__ __forceinline__ float sortable2f(uint32_t k) {
    uint32_t b = (k & 0x80000000u) ? (k ^ 0x80000000u) : ~k;
    return __uint_as_float(b);
}

// ---- GEMM: R7 skeleton (2-slot, 2-sync, reg-staged), fp16 2-term ----
__global__ __launch_bounds__(256, 1)
void gate_gemm_kernel(const float* __restrict__ x) {
    extern __shared__ char smem[];
    __half* xs = reinterpret_cast<__half*>(smem);                     // [2][BM][XSB]
    uint4* wsm = reinterpret_cast<uint4*>(smem + 2 * X_SLOT * 2);     // [2][4ks][4tg][64e]

    const int tid  = threadIdx.x;
    const int warp = tid >> 5;
    const int lane = tid & 31;
    const int g    = lane >> 2;
    const int tg   = lane & 3;
    const int tile  = blockIdx.x >> 1;
    const int split = blockIdx.x & 1;
    const int mBase = tile * BM;
    const int kBase = split * KSPAN;

    float acc[8][4];
#pragma unroll
    for (int i = 0; i < 8; i++)
#pragma unroll
        for (int j = 0; j < 4; j++) acc[i][j] = 0.f;

    float4 xr[8];
    uint4  wr[4];

    auto load_regs = [&](int c) {       // c = local chunk
        const int k0 = kBase + c * KC;
#pragma unroll
        for (int i = 0; i < 8; i++) {               // 128 rows x 16 float4
            int idx = tid + i * 256;
            int row = idx >> 4, c4 = idx & 15;
            xr[i] = *reinterpret_cast<const float4*>(
                x + (size_t)(mBase + row) * HDIM + k0 + c4 * 4);
        }
        const uint4* wsrc = g_w_pack + (size_t)(k0 >> 6) * 1024;
#pragma unroll
        for (int i = 0; i < 4; i++)
            wr[i] = wsrc[tid + i * 256];
    };
    auto store_regs = [&](int slot) {
        __half* xb = xs + slot * X_SLOT;
#pragma unroll
        for (int i = 0; i < 8; i++) {
            int idx = tid + i * 256;
            int row = idx >> 4, c4 = idx & 15;
            float4 f = xr[i];
            __half2 p01 = __floats2half2_rn(f.x, f.y);
            __half2 p23 = __floats2half2_rn(f.z, f.w);
            uint2 pp = make_uint2(*reinterpret_cast<uint32_t*>(&p01),
                                  *reinterpret_cast<uint32_t*>(&p23));
            *reinterpret_cast<uint2*>(xb + row * XSB + c4 * 4) = pp;
        }
        uint4* wb = wsm + slot * W_SLOT;
#pragma unroll
        for (int i = 0; i < 4; i++) {
            int idx = tid + i * 256;                 // [ks(4)][e(64)][tg(4)] src order
            int ks = idx >> 8, e = (idx >> 2) & 63, t4 = idx & 3;
            wb[(ks * 4 + t4) * 64 + e] = wr[i];      // dst: [ks][tg][e] contiguous
        }
    };

    load_regs(0);
    store_regs(0);
    __syncthreads();

    for (int c = 0; c < NCHUNK; c++) {
        const int buf = c & 1;
        if (c + 1 < NCHUNK) load_regs(c + 1);

        const __half* xb = xs + buf * X_SLOT + warp * 16 * XSB;
        const uint4* wb = wsm + buf * W_SLOT;

#pragma unroll
        for (int ks = 0; ks < 4; ks++) {
            const int k0 = ks * 16;
            uint32_t ah[4];
            ah[0] = *reinterpret_cast<const uint32_t*>(xb + g * XSB + k0 + tg * 2);
            ah[1] = *reinterpret_cast<const uint32_t*>(xb + (g + 8) * XSB + k0 + tg * 2);
            ah[2] = *reinterpret_cast<const uint32_t*>(xb + g * XSB + k0 + tg * 2 + 8);
            ah[3] = *reinterpret_cast<const uint32_t*>(xb + (g + 8) * XSB + k0 + tg * 2 + 8);
            const uint4* wbt = wb + (ks * 4 + tg) * 64 + g;
#pragma unroll
            for (int nt = 0; nt < 8; nt++) {
                uint4 wv = wbt[nt * 8];
                mma_fp16(acc[nt], ah, wv.x, wv.y);   // x * w_hi
                mma_fp16(acc[nt], ah, wv.z, wv.w);   // x * w_lo
            }
        }
        __syncthreads();
        if (c + 1 < NCHUNK) {
            store_regs(buf ^ 1);
            __syncthreads();
        }
    }

    // write fp32 partial logits for this K-half
    const int n0 = mBase + warp * 16 + g;
    const int n1 = n0 + 8;
    float* p = g_part + (size_t)split * NTOK * NEXP;
#pragma unroll
    for (int nt = 0; nt < 8; nt++) {
        const int e = nt * 8 + tg * 2;
        *reinterpret_cast<float2*>(p + (size_t)n0 * NEXP + e) =
            make_float2(acc[nt][0], acc[nt][1]);
        *reinterpret_cast<float2*>(p + (size_t)n1 * NEXP + e) =
            make_float2(acc[nt][2], acc[nt][3]);
    }
}

// ---- reduce: partials + noise -> FTZ softmax + top-2; flag tight margins ----
__global__ __launch_bounds__(256)
void gate_reduce_kernel(const float* __restrict__ noise,
                        float* __restrict__ out) {
    const int n = blockIdx.x * 256 + threadIdx.x;
    if (n >= NTOK) return;

    float v[NEXP];
#pragma unroll
    for (int q = 0; q < NEXP / 4; q++) {
        float4 a = *reinterpret_cast<const float4*>(g_part + (size_t)n * NEXP + q * 4);
        float4 b = *reinterpret_cast<const float4*>(
            g_part + (size_t)NTOK * NEXP + (size_t)n * NEXP + q * 4);
        float4 nz = *reinterpret_cast<const float4*>(noise + (size_t)n * NEXP + q * 4);
        v[q * 4 + 0] = a.x + b.x + nz.x;
        v[q * 4 + 1] = a.y + b.y + nz.y;
        v[q * 4 + 2] = a.z + b.z + nz.z;
        v[q * 4 + 3] = a.w + b.w + nz.w;
    }

    // FTZ/DAZ softmax semantics (XLA:CPU ScopedFlushDenormal, proven R7):
    // score == 0 exactly when exp(d) < FLT_MIN * s; zero-ties -> lowest index.
    float m = -3.4e38f;
#pragma unroll 8
    for (int e = 0; e < NEXP; e++) m = fmaxf(m, v[e]);
    float s = 0.f;
#pragma unroll 8
    for (int e = 0; e < NEXP; e++) s += __expf(v[e] - m);
    const float flushLim = FLT_MIN_NORMAL * s;

    bool flag = false;
    unsigned long long k1 = 0ull, k2 = 0ull, k3 = 0ull;
#pragma unroll 8
    for (int e = 0; e < NEXP; e++) {
        float d = v[e] - m;
        float ed = __expf(d);
        if (fabsf(ed - flushLim) < 0.005f * flushLim) flag = true;  // flush boundary
        uint32_t k32 = (ed < flushLim) ? 0u : f2sortable(d);
        unsigned long long key =
            ((unsigned long long)k32 << 32) | (unsigned long long)(64 - e);
        if (key > k1) { k3 = k2; k2 = k1; k1 = key; }
        else if (key > k2) { k3 = k2; k2 = key; }
        else if (key > k3) { k3 = key; }
    }

    uint32_t h1 = (uint32_t)(k1 >> 32), h2 = (uint32_t)(k2 >> 32), h3 = (uint32_t)(k3 >> 32);
    if (h2 != 0u) {
        float d1 = sortable2f(h1), d2 = sortable2f(h2);
        if (d1 - d2 < MARGIN) flag = true;
        if (h3 != 0u) {
            float d3 = sortable2f(h3);
            if (d2 - d3 < MARGIN) flag = true;
        }
    }
    if (flag) {
        int i = atomicAdd(&g_nflag, 1);
        g_flags[i] = n;
    }

    int i1 = 64 - (int)(k1 & 0xffffffffull);
    int i2 = 64 - (int)(k2 & 0xffffffffull);
    float inv = 1.0f / s;
    float w1 = (h1 == 0u) ? 0.f : __expf(sortable2f(h1)) * inv;
    float w2 = (h2 == 0u) ? 0.f : __expf(sortable2f(h2)) * inv;
    *reinterpret_cast<float2*>(out + 2 * n) = make_float2((float)i1, (float)i2);
    *reinterpret_cast<float2*>(out + 2 * NTOK + 2 * n) = make_float2(w1, w2);
}

// ---- patch: recompute flagged tokens exactly in fp32, overwrite out ----
__global__ __launch_bounds__(256)
void gate_patch_kernel(const float* __restrict__ x,
                       const float* __restrict__ w,
                       const float* __restrict__ noise,
                       float* __restrict__ out) {
    __shared__ float pv[NEXP][4];
    __shared__ float sv[NEXP];
    const int tid = threadIdx.x;
    const int e = tid >> 2, q = tid & 3;
    const int nf = g_nflag;

    for (int t = blockIdx.x; t < nf; t += gridDim.x) {
        const int n = g_flags[t];
        const float* xr = x + (size_t)n * HDIM + q * (HDIM / 4);
        const float* wr = w + (size_t)e * HDIM + q * (HDIM / 4);
        float p0 = 0.f, p1 = 0.f, p2 = 0.f, p3 = 0.f;
#pragma unroll 4
        for (int k = 0; k < HDIM / 4; k += 4) {
            float4 xv = *reinterpret_cast<const float4*>(xr + k);
            float4 wv = *reinterpret_cast<const float4*>(wr + k);
            p0 = fmaf(xv.x, wv.x, p0);
            p1 = fmaf(xv.y, wv.y, p1);
            p2 = fmaf(xv.z, wv.z, p2);
            p3 = fmaf(xv.w, wv.w, p3);
        }
        pv[e][q] = (p0 + p1) + (p2 + p3);
        __syncthreads();
        if (tid < NEXP)
            sv[tid] = ((pv[tid][0] + pv[tid][1]) + (pv[tid][2] + pv[tid][3]))
                      + noise[(size_t)n * NEXP + tid];
        __syncthreads();
        if (tid == 0) {
            float m = -3.4e38f;
            for (int ee = 0; ee < NEXP; ee++) m = fmaxf(m, sv[ee]);
            float s = 0.f;
            for (int ee = 0; ee < NEXP; ee++) s += __expf(sv[ee] - m);
            const float flushLim = FLT_MIN_NORMAL * s;
            unsigned long long k1 = 0ull, k2 = 0ull;
            for (int ee = 0; ee < NEXP; ee++) {
                float d = sv[ee] - m;
                float ed = __expf(d);
                uint32_t k32 = (ed < flushLim) ? 0u : f2sortable(d);
                unsigned long long key =
                    ((unsigned long long)k32 << 32) | (unsigned long long)(64 - ee);
                if (key > k1) { k2 = k1; k1 = key; }
                else if (key > k2) { k2 = key; }
            }
            int i1 = 64 - (int)(k1 & 0xffffffffull);
            int i2 = 64 - (int)(k2 & 0xffffffffull);
            uint32_t h1 = (uint32_t)(k1 >> 32), h2 = (uint32_t)(k2 >> 32);
            float inv = 1.0f / s;
            float w1 = (h1 == 0u) ? 0.f : __expf(sortable2f(h1)) * inv;
            float w2 = (h2 == 0u) ? 0.f : __expf(sortable2f(h2)) * inv;
            *reinterpret_cast<float2*>(out + 2 * n) = make_float2((float)i1, (float)i2);
            *reinterpret_cast<float2*>(out + 2 * NTOK + 2 * n) = make_float2(w1, w2);
        }
        __syncthreads();
    }
}

extern "C" void kernel_launch(void* const* d_in, const int* in_sizes, int n_in,
                              void* d_out, int out_size) {
    const float* x     = (const float*)d_in[0];  // hidden_states [4,4096,4096]
    const float* w     = (const float*)d_in[1];  // weight [64,4096]
    const float* noise = (const float*)d_in[2];  // noise [16384,64]
    float* out = (float*)d_out;

    cudaFuncSetAttribute(gate_gemm_kernel,
                         cudaFuncAttributeMaxDynamicSharedMemorySize, SMEM_BYTES);

    prep_w_kernel<<<(NKS * NEXP * 4 + 255) / 256, 256>>>(w);
    gate_gemm_kernel<<<(NTOK / BM) * SPLITK, 256, SMEM_BYTES>>>(x);
    gate_reduce_kernel<<<NTOK / 256, 256>>>(noise, out);
    gate_patch_kernel<<<128, 256>>>(x, w, noise, out);
}

// round 15
// speedup vs baseline: 2.4965x; 2.4965x over previous
#include <cuda_runtime.h>
#include <cuda_bf16.h>
#include <cstdint>

#define NTOK 16384
#define HDIM 4096
#define NEXP 64
#define BM   128
#define KC   64
#define SPLITK 2
#define KSPAN (HDIM / SPLITK)        // 2048
#define NCHUNK (KSPAN / KC)          // 32
#define XS   (KC + 8)                // x smem row stride (floats) = 72 (288B, 16B-aligned)
#define WS   (KC + 8)                // w smem row stride (bf16)  = 72 (144B, 16B-aligned)
#define SMEM_X_BYTES (2 * BM * XS * 4)            // 73728
#define SMEM_W_BYTES (2 * NEXP * WS * 2)          // 18432 per array
#define SMEM_BYTES   (SMEM_X_BYTES + 2 * SMEM_W_BYTES)  // 110592 -> 2 CTAs/SM

#define FLT_MIN_NORMAL 1.17549435e-38f

// Pre-split W (fp32 -> bf16 hi + lo), 1 MB, L2-resident.
__device__ __nv_bfloat16 g_w_hi[NEXP * HDIM];
__device__ __nv_bfloat16 g_w_lo[NEXP * HDIM];
// Split-K partial logits [SPLITK][NTOK][NEXP] fp32 = 8 MB.
__device__ float g_part[SPLITK * NTOK * NEXP];

__global__ void prep_w_kernel(const float* __restrict__ w) {
    int i = blockIdx.x * blockDim.x + threadIdx.x;
    if (i < NEXP * HDIM) {
        float v = w[i];
        __nv_bfloat16 hi = __float2bfloat16_rn(v);
        float r = v - __bfloat162float(hi);
        g_w_hi[i] = hi;
        g_w_lo[i] = __float2bfloat16_rn(r);
    }
}

__device__ __forceinline__ void mma_bf16(float* c, const uint32_t* a,
                                         uint32_t b0, uint32_t b1) {
    asm volatile(
        "mma.sync.aligned.m16n8k16.row.col.f32.bf16.bf16.f32 "
        "{%0,%1,%2,%3}, {%4,%5,%6,%7}, {%8,%9}, {%0,%1,%2,%3};\n"
        : "+f"(c[0]), "+f"(c[1]), "+f"(c[2]), "+f"(c[3])
        : "r"(a[0]), "r"(a[1]), "r"(a[2]), "r"(a[3]), "r"(b0), "r"(b1));
}

__device__ __forceinline__ void cvt_split(float2 f, uint32_t& hi, uint32_t& lo) {
    __nv_bfloat162 h = __floats2bfloat162_rn(f.x, f.y);
    float rx = f.x - __bfloat162float(h.x);
    float ry = f.y - __bfloat162float(h.y);
    __nv_bfloat162 l = __floats2bfloat162_rn(rx, ry);
    hi = *reinterpret_cast<uint32_t*>(&h);
    lo = *reinterpret_cast<uint32_t*>(&l);
}

__device__ __forceinline__ void cp16(void* smem_dst, const void* gmem_src) {
    uint32_t s = (uint32_t)__cvta_generic_to_shared(smem_dst);
    asm volatile("cp.async.cg.shared.global [%0], [%1], 16;\n" :: "r"(s), "l"(gmem_src));
}

__device__ __forceinline__ uint32_t f2sortable(float f) {
    uint32_t b = __float_as_uint(f);
    return b ^ (((int32_t)b >> 31) | 0x80000000u);
}
__device__ __forceinline__ float sortable2f(uint32_t k) {
    uint32_t b = (k & 0x80000000u) ? (k ^ 0x80000000u) : ~k;
    return __uint_as_float(b);
}

// ---- GEMM: R7-exact mainloop; cp.async staging; split-K=2; 2 CTAs/SM ----
__global__ __launch_bounds__(256, 2)
void gate_gemm_kernel(const float* __restrict__ x) {
    extern __shared__ char smem[];
    float* xs = reinterpret_cast<float*>(smem);                       // [2][BM][XS]
    __nv_bfloat16* wh = reinterpret_cast<__nv_bfloat16*>(smem + SMEM_X_BYTES); // [2][NEXP][WS]
    __nv_bfloat16* wl = wh + 2 * NEXP * WS;

    const int tid  = threadIdx.x;
    const int warp = tid >> 5;
    const int lane = tid & 31;
    const int g    = lane >> 2;
    const int tg   = lane & 3;
    const int tile  = blockIdx.x >> 1;
    const int split = blockIdx.x & 1;
    const int mBase = tile * BM;
    const int kBase = split * KSPAN;

    float acc[8][4];
#pragma unroll
    for (int i = 0; i < 8; i++)
#pragma unroll
        for (int j = 0; j < 4; j++) acc[i][j] = 0.f;

    // stage chunk c (local) into slot via cp.async; one commit group per stage
    auto issue_stage = [&](int c, int slot) {
        const int k0 = kBase + c * KC;
        float* xb = xs + slot * BM * XS;
#pragma unroll
        for (int i = 0; i < 8; i++) {                 // 128 rows x 16 float4 = 2048
            int idx = tid + i * 256;
            int row = idx >> 4, c4 = idx & 15;
            cp16(xb + row * XS + c4 * 4,
                 x + (size_t)(mBase + row) * HDIM + k0 + c4 * 4);
        }
        __nv_bfloat16* whb = wh + slot * NEXP * WS;
        __nv_bfloat16* wlb = wl + slot * NEXP * WS;
#pragma unroll
        for (int i = 0; i < 2; i++) {                 // 64 rows x 8 granules = 512
            int idx = tid + i * 256;
            int row = idx >> 3, q = idx & 7;
            cp16(whb + row * WS + q * 8, g_w_hi + (size_t)row * HDIM + k0 + q * 8);
            cp16(wlb + row * WS + q * 8, g_w_lo + (size_t)row * HDIM + k0 + q * 8);
        }
        asm volatile("cp.async.commit_group;\n" ::: "memory");
    };

    // prologue: stages 0,1 in flight; wait for stage 0
    issue_stage(0, 0);
    issue_stage(1, 1);
    asm volatile("cp.async.wait_group 1;\n" ::: "memory");
    __syncthreads();

    for (int c = 0; c < NCHUNK; c++) {
        const int buf = c & 1;

        // ---- compute chunk c (R7-exact fragment/LDS/MMA pattern) ----
        const float* xb = xs + buf * BM * XS + warp * 16 * XS;
        const __nv_bfloat16* whb = wh + buf * NEXP * WS;
        const __nv_bfloat16* wlb = wl + buf * NEXP * WS;

#pragma unroll
        for (int ks = 0; ks < KC / 16; ks++) {
            const int k0 = ks * 16;
            float2 f00 = *reinterpret_cast<const float2*>(xb + g * XS + k0 + tg * 2);
            float2 f01 = *reinterpret_cast<const float2*>(xb + g * XS + k0 + tg * 2 + 8);
            float2 f10 = *reinterpret_cast<const float2*>(xb + (g + 8) * XS + k0 + tg * 2);
            float2 f11 = *reinterpret_cast<const float2*>(xb + (g + 8) * XS + k0 + tg * 2 + 8);
            uint32_t ah[4], al[4];
            cvt_split(f00, ah[0], al[0]);
            cvt_split(f10, ah[1], al[1]);
            cvt_split(f01, ah[2], al[2]);
            cvt_split(f11, ah[3], al[3]);
#pragma unroll
            for (int nt = 0; nt < 8; nt++) {
                const int e = nt * 8 + g;
                uint32_t bh0 = *reinterpret_cast<const uint32_t*>(whb + e * WS + k0 + tg * 2);
                uint32_t bh1 = *reinterpret_cast<const uint32_t*>(whb + e * WS + k0 + tg * 2 + 8);
                uint32_t bl0 = *reinterpret_cast<const uint32_t*>(wlb + e * WS + k0 + tg * 2);
                uint32_t bl1 = *reinterpret_cast<const uint32_t*>(wlb + e * WS + k0 + tg * 2 + 8);
                mma_bf16(acc[nt], ah, bh0, bh1);   // hi*hi
                mma_bf16(acc[nt], ah, bl0, bl1);   // hi*lo
                mma_bf16(acc[nt], al, bh0, bh1);   // lo*hi
            }
        }
        __syncthreads();                   // all warps done reading slot buf

        if (c + 2 < NCHUNK) {
            issue_stage(c + 2, buf);       // refill freed slot
            asm volatile("cp.async.wait_group 1;\n" ::: "memory");  // c+1 arrived
            __syncthreads();
        } else if (c + 1 < NCHUNK) {
            asm volatile("cp.async.wait_group 0;\n" ::: "memory");  // drain c+1
            __syncthreads();
        }
    }

    // write fp32 partial logits for this K-half
    const int n0 = mBase + warp * 16 + g;
    const int n1 = n0 + 8;
    float* p = g_part + (size_t)split * NTOK * NEXP;
#pragma unroll
    for (int nt = 0; nt < 8; nt++) {
        const int e = nt * 8 + tg * 2;
        *reinterpret_cast<float2*>(p + (size_t)n0 * NEXP + e) =
            make_float2(acc[nt][0], acc[nt][1]);
        *reinterpret_cast<float2*>(p + (size_t)n1 * NEXP + e) =
            make_float2(acc[nt][2], acc[nt][3]);
    }
}

// ---- reduce: partials + noise -> FTZ softmax + top-2 (R13-proven) ----
__global__ __launch_bounds__(256)
void gate_reduce_kernel(const float* __restrict__ noise,
                        float* __restrict__ out) {
    const int n = blockIdx.x * 256 + threadIdx.x;
    if (n >= NTOK) return;

    float v[NEXP];
#pragma unroll
    for (int q = 0; q < NEXP / 4; q++) {
        float4 a = *reinterpret_cast<const float4*>(g_part + (size_t)n * NEXP + q * 4);
        float4 b = *reinterpret_cast<const float4*>(
            g_part + (size_t)NTOK * NEXP + (size_t)n * NEXP + q * 4);
        float4 nz = *reinterpret_cast<const float4*>(noise + (size_t)n * NEXP + q * 4);
        v[q * 4 + 0] = a.x + b.x + nz.x;
        v[q * 4 + 1] = a.y + b.y + nz.y;
        v[q * 4 + 2] = a.z + b.z + nz.z;
        v[q * 4 + 3] = a.w + b.w + nz.w;
    }

    // FTZ/DAZ softmax semantics (XLA:CPU ScopedFlushDenormal): score flushes
    // to exactly 0 when fl(exp(d))/s is subnormal, i.e. exp(d) < FLT_MIN * s;
    // flushed experts tie at 0 -> lowest index wins (jax top_k). Above the
    // flush line score order == order of d.
    float m = -3.4e38f;
#pragma unroll 8
    for (int e = 0; e < NEXP; e++) m = fmaxf(m, v[e]);
    float s = 0.f;
#pragma unroll 8
    for (int e = 0; e < NEXP; e++) s += __expf(v[e] - m);
    const float flushLim = FLT_MIN_NORMAL * s;

    unsigned long long k1 = 0ull, k2 = 0ull;
#pragma unroll 8
    for (int e = 0; e < NEXP; e++) {
        float d = v[e] - m;
        float ed = __expf(d);
        uint32_t k32 = (ed < flushLim) ? 0u : f2sortable(d);
        unsigned long long key =
            ((unsigned long long)k32 << 32) | (unsigned long long)(64 - e);
        if (key > k1) { k2 = k1; k1 = key; }
        else if (key > k2) { k2 = key; }
    }

    int i1 = 64 - (int)(k1 & 0xffffffffull);
    int i2 = 64 - (int)(k2 & 0xffffffffull);
    uint32_t h1 = (uint32_t)(k1 >> 32), h2 = (uint32_t)(k2 >> 32);
    float inv = 1.0f / s;
    float w1 = (h1 == 0u) ? 0.f : __expf(sortable2f(h1)) * inv;
    float w2 = (h2 == 0u) ? 0.f : __expf(sortable2f(h2)) * inv;
    // layout: [topk_idx as float (N*2)] then [topk_weight (N*2)]
    *reinterpret_cast<float2*>(out + 2 * n) = make_float2((float)i1, (float)i2);
    *reinterpret_cast<float2*>(out + 2 * NTOK + 2 * n) = make_float2(w1, w2);
}

extern "C" void kernel_launch(void* const* d_in, const int* in_sizes, int n_in,
                              void* d_out, int out_size) {
    const float* x     = (const float*)d_in[0];  // hidden_states [4,4096,4096]
    const float* w     = (const float*)d_in[1];  // weight [64,4096]
    const float* noise = (const float*)d_in[2];  // noise [16384,64]
    float* out = (float*)d_out;

    cudaFuncSetAttribute(gate_gemm_kernel,
                         cudaFuncAttributeMaxDynamicSharedMemorySize, SMEM_BYTES);

    prep_w_kernel<<<(NEXP * HDIM + 255) / 256, 256>>>(w);
    gate_gemm_kernel<<<(NTOK / BM) * SPLITK, 256, SMEM_BYTES>>>(x);
    gate_reduce_kernel<<<NTOK / 256, 256>>>(noise, out);
}